// round 2
// baseline (speedup 1.0000x reference)
#include <cuda_runtime.h>
#include <math.h>

#define BB 32
#define CC 256
#define HWD 96
#define PLANE (HWD*HWD)      // 9216
#define NPLANES (BB*CC)      // 8192
#define KK 9
#define W2ROWS (CC*KK)       // 2304

// scratch (no allocations allowed)
__device__ float g_pooled[BB*CC];
__device__ float g_wdyn[BB*CC*KK];

// ---------------------------------------------------------------------------
// Kernel 1: global average pool per (b,c) plane. 1 block = 1 plane.
// ---------------------------------------------------------------------------
__global__ __launch_bounds__(256) void pool_kernel(const float* __restrict__ x) {
    const int plane = blockIdx.x;
    const float4* __restrict__ xp =
        reinterpret_cast<const float4*>(x + (size_t)plane * PLANE);
    float sum = 0.f;
#pragma unroll
    for (int it = 0; it < 9; ++it) {               // 9216/4/256 = 9
        float4 v = xp[threadIdx.x + it * 256];
        sum += (v.x + v.y) + (v.z + v.w);
    }
#pragma unroll
    for (int o = 16; o > 0; o >>= 1)
        sum += __shfl_xor_sync(0xffffffffu, sum, o);
    __shared__ float ws[8];
    const int lane = threadIdx.x & 31, wid = threadIdx.x >> 5;
    if (lane == 0) ws[wid] = sum;
    __syncthreads();
    if (threadIdx.x == 0) {
        float t = 0.f;
#pragma unroll
        for (int i = 0; i < 8; ++i) t += ws[i];
        g_pooled[plane] = t * (1.0f / (float)PLANE);
    }
}

// ---------------------------------------------------------------------------
// Kernel 2: dynamic net. 1 block = 1 batch sample.
//   h    = gelu(pooled @ w1^T + b1)        (exact gelu, erf)
//   wdyn = h @ w2^T + b2                   (2304 per sample)
// ---------------------------------------------------------------------------
__global__ __launch_bounds__(256) void dyn_kernel(const float* __restrict__ w1,
                                                  const float* __restrict__ b1,
                                                  const float* __restrict__ w2,
                                                  const float* __restrict__ b2) {
    const int b = blockIdx.x;
    const int c = threadIdx.x;
    __shared__ float ps[CC];
    __shared__ float hs[CC];
    ps[c] = g_pooled[b * CC + c];
    __syncthreads();

    // h[c] = gelu(b1[c] + sum_k pooled[k] * w1[c][k])
    {
        float acc = b1[c];
        const float4* __restrict__ wr =
            reinterpret_cast<const float4*>(w1 + (size_t)c * CC);
        const float4* __restrict__ pv = reinterpret_cast<const float4*>(ps);
#pragma unroll 8
        for (int k = 0; k < CC / 4; ++k) {
            float4 a = pv[k];
            float4 w = wr[k];
            acc += a.x * w.x + a.y * w.y + a.z * w.z + a.w * w.w;
        }
        // exact GELU: 0.5*x*(1+erf(x/sqrt(2)))
        hs[c] = 0.5f * acc * (1.0f + erff(acc * 0.70710678118654752f));
    }
    __syncthreads();

    // wdyn[r] = b2[r] + sum_k h[k] * w2[r][k],  r = tid + r0*256
    const float4* __restrict__ hv = reinterpret_cast<const float4*>(hs);
#pragma unroll
    for (int r0 = 0; r0 < KK; ++r0) {
        const int r = threadIdx.x + r0 * 256;
        float acc = b2[r];
        const float4* __restrict__ wr =
            reinterpret_cast<const float4*>(w2 + (size_t)r * CC);
#pragma unroll 8
        for (int k = 0; k < CC / 4; ++k) {
            float4 a = hv[k];
            float4 w = wr[k];
            acc += a.x * w.x + a.y * w.y + a.z * w.z + a.w * w.w;
        }
        g_wdyn[b * W2ROWS + r] = acc;
    }
}

// ---------------------------------------------------------------------------
// Kernel 3: per-plane 3x3 dynamic stencil with reflect padding.
// 1 block = 1 (b,c) plane staged in shared memory.
// ---------------------------------------------------------------------------
__global__ __launch_bounds__(256) void conv_kernel(const float* __restrict__ x,
                                                   float* __restrict__ out) {
    const int plane = blockIdx.x;
    __shared__ float s[PLANE];

    const float4* __restrict__ xp =
        reinterpret_cast<const float4*>(x + (size_t)plane * PLANE);
    float4* sp = reinterpret_cast<float4*>(s);
#pragma unroll
    for (int it = 0; it < 9; ++it)
        sp[threadIdx.x + it * 256] = xp[threadIdx.x + it * 256];

    float w[KK];
    const float* __restrict__ wd = g_wdyn + (size_t)plane * KK;
#pragma unroll
    for (int i = 0; i < KK; ++i) w[i] = wd[i];
    __syncthreads();

    float* __restrict__ o = out + (size_t)plane * PLANE;
#pragma unroll
    for (int it = 0; it < 36; ++it) {
        const int p = threadIdx.x + it * 256;
        const int y = p / HWD;
        const int xx = p - y * HWD;
        // reflect (no edge repeat): -1 -> 1, H -> H-2
        const int ym = (y == 0) ? 1 : y - 1;
        const int yp = (y == HWD - 1) ? HWD - 2 : y + 1;
        const int xm = (xx == 0) ? 1 : xx - 1;
        const int xq = (xx == HWD - 1) ? HWD - 2 : xx + 1;

        const float* r0 = s + ym * HWD;
        const float* r1 = s + y * HWD;
        const float* r2 = s + yp * HWD;
        float acc = r0[xm] * w[0] + r0[xx] * w[1] + r0[xq] * w[2]
                  + r1[xm] * w[3] + r1[xx] * w[4] + r1[xq] * w[5]
                  + r2[xm] * w[6] + r2[xx] * w[7] + r2[xq] * w[8];
        o[p] = acc;
    }
}

// ---------------------------------------------------------------------------
extern "C" void kernel_launch(void* const* d_in, const int* in_sizes, int n_in,
                              void* d_out, int out_size) {
    const float* x  = (const float*)d_in[0];   // (32,256,96,96)
    const float* w1 = (const float*)d_in[1];   // (256,256)
    const float* b1 = (const float*)d_in[2];   // (256,)
    const float* w2 = (const float*)d_in[3];   // (2304,256)
    const float* b2 = (const float*)d_in[4];   // (2304,)
    float* out = (float*)d_out;

    pool_kernel<<<NPLANES, 256>>>(x);
    dyn_kernel<<<BB, 256>>>(w1, b1, w2, b2);
    conv_kernel<<<NPLANES, 256>>>(x, out);
}

// round 3
// speedup vs baseline: 1.3136x; 1.3136x over previous
#include <cuda_runtime.h>
#include <math.h>

#define BB 32
#define CC 256
#define HWD 96
#define ROW4 (HWD/4)         // 24 float4 per row
#define PLANE (HWD*HWD)      // 9216
#define PLANE4 (PLANE/4)     // 2304
#define NPLANES (BB*CC)      // 8192
#define KK 9
#define W2ROWS (CC*KK)       // 2304

// scratch (no allocations allowed)
__device__ float g_pooled[BB*CC];
__device__ float g_wdyn[BB*CC*KK];

// ---------------------------------------------------------------------------
// Kernel 1: global average pool per (b,c) plane. 1 block = 1 plane.
// Already at ~85% DRAM roofline.
// ---------------------------------------------------------------------------
__global__ __launch_bounds__(256) void pool_kernel(const float* __restrict__ x) {
    const int plane = blockIdx.x;
    const float4* __restrict__ xp =
        reinterpret_cast<const float4*>(x + (size_t)plane * PLANE);
    float sum = 0.f;
#pragma unroll
    for (int it = 0; it < 9; ++it) {               // 9216/4/256 = 9
        float4 v = xp[threadIdx.x + it * 256];
        sum += (v.x + v.y) + (v.z + v.w);
    }
#pragma unroll
    for (int o = 16; o > 0; o >>= 1)
        sum += __shfl_xor_sync(0xffffffffu, sum, o);
    __shared__ float ws[8];
    const int lane = threadIdx.x & 31, wid = threadIdx.x >> 5;
    if (lane == 0) ws[wid] = sum;
    __syncthreads();
    if (threadIdx.x == 0) {
        float t = 0.f;
#pragma unroll
        for (int i = 0; i < 8; ++i) t += ws[i];
        g_pooled[plane] = t * (1.0f / (float)PLANE);
    }
}

// ---------------------------------------------------------------------------
// Kernel 2: dynamic net, parallelized. grid = (9, 32).
// Block (r0, b): recompute h = gelu(pooled[b] @ w1^T + b1) (cheap),
// then each thread computes one row r = r0*256+tid of wdyn[b].
// ---------------------------------------------------------------------------
__global__ __launch_bounds__(256) void dyn_kernel(const float* __restrict__ w1,
                                                  const float* __restrict__ b1,
                                                  const float* __restrict__ w2,
                                                  const float* __restrict__ b2) {
    const int b  = blockIdx.y;
    const int r0 = blockIdx.x;
    const int c  = threadIdx.x;
    __shared__ float ps[CC];
    __shared__ float hs[CC];
    ps[c] = g_pooled[b * CC + c];
    __syncthreads();

    // h[c] = gelu(b1[c] + sum_k pooled[k] * w1[c][k])
    {
        float acc = b1[c];
        const float4* __restrict__ wr =
            reinterpret_cast<const float4*>(w1 + (size_t)c * CC);
        const float4* __restrict__ pv = reinterpret_cast<const float4*>(ps);
#pragma unroll 8
        for (int k = 0; k < CC / 4; ++k) {
            float4 a = pv[k];
            float4 w = wr[k];
            acc += a.x * w.x + a.y * w.y + a.z * w.z + a.w * w.w;
        }
        hs[c] = 0.5f * acc * (1.0f + erff(acc * 0.70710678118654752f));
    }
    __syncthreads();

    // wdyn[b][r] = b2[r] + sum_k h[k] * w2[r][k]
    const int r = r0 * 256 + c;
    float acc = b2[r];
    const float4* __restrict__ wr =
        reinterpret_cast<const float4*>(w2 + (size_t)r * CC);
    const float4* __restrict__ hv = reinterpret_cast<const float4*>(hs);
#pragma unroll 8
    for (int k = 0; k < CC / 4; ++k) {
        float4 a = hv[k];
        float4 w = wr[k];
        acc += a.x * w.x + a.y * w.y + a.z * w.z + a.w * w.w;
    }
    g_wdyn[(size_t)b * W2ROWS + r] = acc;
}

// ---------------------------------------------------------------------------
// Kernel 3 v2: per-plane 3x3 dynamic stencil, float4-vectorized.
// 1 block = 1 (b,c) plane in shared. Each thread: 9 groups of 4 pixels.
// Per stencil row per group: 1 LDS.128 + <=2 scalar LDS (reflect-specialized).
// ---------------------------------------------------------------------------
__global__ __launch_bounds__(256) void conv_kernel(const float* __restrict__ x,
                                                   float* __restrict__ out) {
    const int plane = blockIdx.x;
    __shared__ float s[PLANE];

    const float4* __restrict__ xp =
        reinterpret_cast<const float4*>(x + (size_t)plane * PLANE);
    float4* sp = reinterpret_cast<float4*>(s);
#pragma unroll
    for (int it = 0; it < 9; ++it)
        sp[threadIdx.x + it * 256] = xp[threadIdx.x + it * 256];

    float w[KK];
    const float* __restrict__ wd = g_wdyn + (size_t)plane * KK;
#pragma unroll
    for (int i = 0; i < KK; ++i) w[i] = wd[i];
    __syncthreads();

    float4* __restrict__ o4 = reinterpret_cast<float4*>(out + (size_t)plane * PLANE);

#pragma unroll
    for (int it = 0; it < 9; ++it) {
        const int p4 = threadIdx.x + it * 256;     // [0, 2304)
        const int y  = p4 / ROW4;
        const int x4 = p4 - y * ROW4;
        const int xb = x4 * 4;                     // pixel column of group start

        // reflect rows (no edge repeat): -1 -> 1, 96 -> 94
        const int ym = (y == 0) ? 1 : y - 1;
        const int yp = (y == HWD - 1) ? HWD - 2 : y + 1;

        const int rows[3] = { ym * HWD, y * HWD, yp * HWD };

        float4 acc = make_float4(0.f, 0.f, 0.f, 0.f);
#pragma unroll
        for (int k = 0; k < 3; ++k) {
            const int rb = rows[k];
            const float wl = w[3 * k + 0];
            const float wc = w[3 * k + 1];
            const float wr = w[3 * k + 2];
            const float4 c = *reinterpret_cast<const float4*>(s + rb + xb);
            // left neighbor of pixel xb: reflect(0-1)=1 == c.y
            const float l = (x4 == 0) ? c.y : s[rb + xb - 1];
            // right neighbor of pixel xb+3: reflect(96)=94 == c.z
            const float r = (x4 == ROW4 - 1) ? c.z : s[rb + xb + 4];

            acc.x += l   * wl + c.x * wc + c.y * wr;
            acc.y += c.x * wl + c.y * wc + c.z * wr;
            acc.z += c.y * wl + c.z * wc + c.w * wr;
            acc.w += c.z * wl + c.w * wc + r   * wr;
        }
        __stcs(&o4[p4], acc);   // streaming store: don't pollute L2
    }
}

// ---------------------------------------------------------------------------
extern "C" void kernel_launch(void* const* d_in, const int* in_sizes, int n_in,
                              void* d_out, int out_size) {
    const float* x  = (const float*)d_in[0];   // (32,256,96,96)
    const float* w1 = (const float*)d_in[1];   // (256,256)
    const float* b1 = (const float*)d_in[2];   // (256,)
    const float* w2 = (const float*)d_in[3];   // (2304,256)
    const float* b2 = (const float*)d_in[4];   // (2304,)
    float* out = (float*)d_out;

    pool_kernel<<<NPLANES, 256>>>(x);
    dyn_kernel<<<dim3(KK, BB), 256>>>(w1, b1, w2, b2);
    conv_kernel<<<NPLANES, 256>>>(x, out);
}